// round 1
// baseline (speedup 1.0000x reference)
#include <cuda_runtime.h>
#include <math.h>
#include <float.h>

#define BB 4
#define SS 2048
#define DIM 512
#define HEADS 8
#define DHEAD 64
#define INNER 512            // HEADS * DHEAD
#define ROWS (BB * SS)       // 8192
#define QKV_STRIDE (3 * INNER)

// Scratch (device globals — no allocation allowed in kernel_launch)
__device__ float g_qkv[ROWS * 3 * INNER];   // [8192, 1536]
__device__ float g_attn[ROWS * INNER];      // [8192, 512]

// ---------------------------------------------------------------------------
// Tiled fp32 GEMM: C[M,N] = A[M,K] @ B[K,N] (+ bias). M%64==0, N%64==0, K%16==0.
// 256 threads, 64x64 tile, 4x4 micro-tile per thread.
// ---------------------------------------------------------------------------
template <bool BIAS>
__global__ void gemm64_kernel(const float* __restrict__ A,
                              const float* __restrict__ Bm,
                              const float* __restrict__ bias,
                              float* __restrict__ C,
                              int M, int N, int K) {
    __shared__ float As[64][17];   // [m][k], padded
    __shared__ float Bs[16][65];   // [k][n], padded

    const int tx = threadIdx.x & 15;
    const int ty = threadIdx.x >> 4;
    const int row0 = blockIdx.y * 64;
    const int col0 = blockIdx.x * 64;

    float acc[4][4] = {};

    for (int k0 = 0; k0 < K; k0 += 16) {
        // A tile: 64x16
        #pragma unroll
        for (int idx = threadIdx.x; idx < 64 * 16; idx += 256) {
            int r = idx >> 4, c = idx & 15;
            As[r][c] = A[(size_t)(row0 + r) * K + k0 + c];
        }
        // B tile: 16x64
        #pragma unroll
        for (int idx = threadIdx.x; idx < 16 * 64; idx += 256) {
            int r = idx >> 6, c = idx & 63;
            Bs[r][c] = Bm[(size_t)(k0 + r) * N + col0 + c];
        }
        __syncthreads();

        #pragma unroll
        for (int k = 0; k < 16; k++) {
            float a[4], b[4];
            #pragma unroll
            for (int i = 0; i < 4; i++) a[i] = As[ty * 4 + i][k];
            #pragma unroll
            for (int j = 0; j < 4; j++) b[j] = Bs[k][tx * 4 + j];
            #pragma unroll
            for (int i = 0; i < 4; i++)
                #pragma unroll
                for (int j = 0; j < 4; j++)
                    acc[i][j] = fmaf(a[i], b[j], acc[i][j]);
        }
        __syncthreads();
    }

    #pragma unroll
    for (int i = 0; i < 4; i++) {
        int r = row0 + ty * 4 + i;
        #pragma unroll
        for (int j = 0; j < 4; j++) {
            int c = col0 + tx * 4 + j;
            float v = acc[i][j];
            if (BIAS) v += bias[c];
            C[(size_t)r * N + c] = v;
        }
    }
}

// ---------------------------------------------------------------------------
// Flash-style attention, fp32. One CTA = one 64-row Q tile of one (b, h).
// Online softmax; diagonal masked to -FLT_MAX; scale = exp(log_temp).
// Dynamic smem: Qs/Ks/Vs/Ps each 64x65 floats = 66560 bytes total.
// ---------------------------------------------------------------------------
__global__ void attn_kernel(const float* __restrict__ qkv,
                            const float* __restrict__ log_temp,
                            float* __restrict__ out) {
    extern __shared__ float sm[];
    float (*Qs)[65] = reinterpret_cast<float(*)[65]>(sm);
    float (*Ks)[65] = reinterpret_cast<float(*)[65]>(sm + 64 * 65);
    float (*Vs)[65] = reinterpret_cast<float(*)[65]>(sm + 2 * 64 * 65);
    float (*Ps)[65] = reinterpret_cast<float(*)[65]>(sm + 3 * 64 * 65);

    const int tx = threadIdx.x & 15;
    const int ty = threadIdx.x >> 4;
    const int bh = blockIdx.y;
    const int b = bh / HEADS;
    const int h = bh % HEADS;
    const int q0 = blockIdx.x * 64;

    const float scale = __expf(*log_temp);

    const float* Qg = qkv + (size_t)(b * SS) * QKV_STRIDE + h * DHEAD;
    const float* Kg = Qg + INNER;
    const float* Vg = Qg + 2 * INNER;

    // Load Q tile [64][64] (rows q0..q0+63, contiguous 64-float chunks)
    #pragma unroll
    for (int idx = threadIdx.x; idx < 64 * 64; idx += 256) {
        int r = idx >> 6, c = idx & 63;
        Qs[r][c] = Qg[(size_t)(q0 + r) * QKV_STRIDE + c];
    }

    float m[4], l[4], O[4][4];
    #pragma unroll
    for (int i = 0; i < 4; i++) {
        m[i] = -FLT_MAX;
        l[i] = 0.f;
        #pragma unroll
        for (int j = 0; j < 4; j++) O[i][j] = 0.f;
    }

    for (int kt = 0; kt < SS / 64; kt++) {
        const int k0 = kt * 64;
        __syncthreads();   // previous iter's P@V done before Ks/Vs overwrite
        #pragma unroll
        for (int idx = threadIdx.x; idx < 64 * 64; idx += 256) {
            int r = idx >> 6, c = idx & 63;
            Ks[r][c] = Kg[(size_t)(k0 + r) * QKV_STRIDE + c];
            Vs[r][c] = Vg[(size_t)(k0 + r) * QKV_STRIDE + c];
        }
        __syncthreads();

        // S = Q @ K^T  (4x4 micro-tile)
        float s[4][4] = {};
        #pragma unroll 8
        for (int d = 0; d < 64; d++) {
            float a[4], kk[4];
            #pragma unroll
            for (int i = 0; i < 4; i++) a[i] = Qs[ty * 4 + i][d];
            #pragma unroll
            for (int j = 0; j < 4; j++) kk[j] = Ks[tx * 4 + j][d];
            #pragma unroll
            for (int i = 0; i < 4; i++)
                #pragma unroll
                for (int j = 0; j < 4; j++)
                    s[i][j] = fmaf(a[i], kk[j], s[i][j]);
        }

        // scale + diagonal mask
        #pragma unroll
        for (int i = 0; i < 4; i++) {
            int qi = q0 + ty * 4 + i;
            #pragma unroll
            for (int j = 0; j < 4; j++) {
                int kj = k0 + tx * 4 + j;
                s[i][j] = (qi == kj) ? -FLT_MAX : s[i][j] * scale;
            }
        }

        // online softmax; row i is owned by the 16 lanes sharing ty
        #pragma unroll
        for (int i = 0; i < 4; i++) {
            float rmax = fmaxf(fmaxf(s[i][0], s[i][1]), fmaxf(s[i][2], s[i][3]));
            #pragma unroll
            for (int off = 8; off >= 1; off >>= 1)
                rmax = fmaxf(rmax, __shfl_xor_sync(0xffffffffu, rmax, off));

            float mnew = fmaxf(m[i], rmax);
            float corr = __expf(m[i] - mnew);
            m[i] = mnew;
            #pragma unroll
            for (int j = 0; j < 4; j++) O[i][j] *= corr;
            l[i] *= corr;

            float ps = 0.f;
            #pragma unroll
            for (int j = 0; j < 4; j++) {
                s[i][j] = __expf(s[i][j] - mnew);
                ps += s[i][j];
            }
            #pragma unroll
            for (int off = 8; off >= 1; off >>= 1)
                ps += __shfl_xor_sync(0xffffffffu, ps, off);
            l[i] += ps;
        }

        // stash P
        #pragma unroll
        for (int i = 0; i < 4; i++)
            #pragma unroll
            for (int j = 0; j < 4; j++)
                Ps[ty * 4 + i][tx * 4 + j] = s[i][j];
        __syncthreads();

        // O += P @ V
        #pragma unroll 8
        for (int k = 0; k < 64; k++) {
            float a[4], vv[4];
            #pragma unroll
            for (int i = 0; i < 4; i++) a[i] = Ps[ty * 4 + i][k];
            #pragma unroll
            for (int j = 0; j < 4; j++) vv[j] = Vs[k][tx * 4 + j];
            #pragma unroll
            for (int i = 0; i < 4; i++)
                #pragma unroll
                for (int j = 0; j < 4; j++)
                    O[i][j] = fmaf(a[i], vv[j], O[i][j]);
        }
    }

    // epilogue: normalize, write [b, s, h*64 + d]
    #pragma unroll
    for (int i = 0; i < 4; i++) {
        float inv_l = 1.f / l[i];
        size_t row = (size_t)(b * SS + q0 + ty * 4 + i);
        #pragma unroll
        for (int j = 0; j < 4; j++)
            out[row * INNER + h * DHEAD + tx * 4 + j] = O[i][j] * inv_l;
    }
}

// ---------------------------------------------------------------------------
extern "C" void kernel_launch(void* const* d_in, const int* in_sizes, int n_in,
                              void* d_out, int out_size) {
    const float* x        = (const float*)d_in[0];   // [4,2048,512]
    const float* W_qkv    = (const float*)d_in[1];   // [512,1536]
    const float* log_temp = (const float*)d_in[2];   // scalar
    const float* W_out    = (const float*)d_in[3];   // [512,512]
    const float* b_out    = (const float*)d_in[4];   // [512]
    float* out = (float*)d_out;                      // [4,2048,512]

    float* qkv_buf = nullptr;
    float* attn_buf = nullptr;
    cudaGetSymbolAddress((void**)&qkv_buf, g_qkv);
    cudaGetSymbolAddress((void**)&attn_buf, g_attn);

    // 1) QKV projection: [8192,512] @ [512,1536]
    {
        dim3 grid(3 * INNER / 64, ROWS / 64);
        gemm64_kernel<false><<<grid, 256>>>(x, W_qkv, nullptr, qkv_buf,
                                            ROWS, 3 * INNER, DIM);
    }

    // 2) attention
    {
        const int smem = 4 * 64 * 65 * (int)sizeof(float);  // 66560 B
        cudaFuncSetAttribute(attn_kernel,
                             cudaFuncAttributeMaxDynamicSharedMemorySize, smem);
        dim3 grid(SS / 64, BB * HEADS);
        attn_kernel<<<grid, 256, smem>>>(qkv_buf, log_temp, attn_buf);
    }

    // 3) output projection + bias: [8192,512] @ [512,512] + b
    {
        dim3 grid(DIM / 64, ROWS / 64);
        gemm64_kernel<true><<<grid, 256>>>(attn_buf, W_out, b_out, out,
                                           ROWS, DIM, INNER);
    }
}

// round 5
// speedup vs baseline: 3.5675x; 3.5675x over previous
#include <cuda_runtime.h>
#include <cuda_bf16.h>
#include <cstdint>
#include <math.h>

typedef __nv_bfloat16 bf16;

#define BB 4
#define SSEQ 2048
#define DIMX 512
#define HEADS 8
#define DHEAD 64
#define INNER 512
#define NROWS (BB * SSEQ)   // 8192

// ---------------- device scratch -------------------------------------------
__device__ bf16 g_xhi[NROWS * DIMX],        g_xlo[NROWS * DIMX];
__device__ bf16 g_wqT_hi[3 * INNER * DIMX], g_wqT_lo[3 * INNER * DIMX];
__device__ bf16 g_woT_hi[DIMX * INNER],     g_woT_lo[DIMX * INNER];
__device__ bf16 g_qhi[NROWS * INNER], g_qlo[NROWS * INNER];  // [bh][s][64]
__device__ bf16 g_khi[NROWS * INNER], g_klo[NROWS * INNER];
__device__ bf16 g_vhi[NROWS * INNER], g_vlo[NROWS * INNER];
__device__ bf16 g_ahi[NROWS * INNER], g_alo[NROWS * INNER];  // [b*s][512]

// ---------------- helpers ---------------------------------------------------
__device__ __forceinline__ uint32_t smem_u32(const void* p) {
    uint32_t a;
    asm("{ .reg .u64 t; cvta.to.shared.u64 t, %1; cvt.u32.u64 %0, t; }" : "=r"(a) : "l"(p));
    return a;
}
__device__ __forceinline__ void ldsm4(uint32_t& r0, uint32_t& r1, uint32_t& r2,
                                      uint32_t& r3, uint32_t addr) {
    asm volatile("ldmatrix.sync.aligned.m8n8.x4.shared.b16 {%0,%1,%2,%3}, [%4];"
                 : "=r"(r0), "=r"(r1), "=r"(r2), "=r"(r3) : "r"(addr));
}
__device__ __forceinline__ void ldsm4t(uint32_t& r0, uint32_t& r1, uint32_t& r2,
                                       uint32_t& r3, uint32_t addr) {
    asm volatile("ldmatrix.sync.aligned.m8n8.x4.trans.shared.b16 {%0,%1,%2,%3}, [%4];"
                 : "=r"(r0), "=r"(r1), "=r"(r2), "=r"(r3) : "r"(addr));
}
__device__ __forceinline__ void mma_bf16(float* c, const uint32_t a[4],
                                         uint32_t b0, uint32_t b1) {
    asm volatile(
        "mma.sync.aligned.m16n8k16.row.col.f32.bf16.bf16.f32 "
        "{%0,%1,%2,%3}, {%4,%5,%6,%7}, {%8,%9}, {%0,%1,%2,%3};"
        : "+f"(c[0]), "+f"(c[1]), "+f"(c[2]), "+f"(c[3])
        : "r"(a[0]), "r"(a[1]), "r"(a[2]), "r"(a[3]), "r"(b0), "r"(b1));
}
__device__ __forceinline__ void cp16(uint32_t dst, const void* src) {
    asm volatile("cp.async.cg.shared.global [%0], [%1], 16;" :: "r"(dst), "l"(src));
}
#define CP_COMMIT() asm volatile("cp.async.commit_group;" ::: "memory")
#define CP_WAIT1()  asm volatile("cp.async.wait_group 1;" ::: "memory")

__device__ __forceinline__ uint32_t pk2(bf16 a, bf16 b) {
    return (uint32_t)__bfloat16_as_ushort(a) | ((uint32_t)__bfloat16_as_ushort(b) << 16);
}
// split two floats into packed bf16x2 hi + lo
__device__ __forceinline__ void split2(float e0, float e1, uint32_t& h, uint32_t& l) {
    bf16 h0 = __float2bfloat16(e0);
    bf16 h1 = __float2bfloat16(e1);
    bf16 l0 = __float2bfloat16(e0 - __bfloat162float(h0));
    bf16 l1 = __float2bfloat16(e1 - __bfloat162float(h1));
    h = pk2(h0, h1);
    l = pk2(l0, l1);
}
// 16B-chunk swizzle within 128B rows (conflict-free ldmatrix)
__device__ __forceinline__ uint32_t swz(int r, int c) {
    return (uint32_t)r * 128u + (uint32_t)((c ^ (r & 7)) & 7) * 16u;
}

// ---------------- convert kernels -------------------------------------------
__global__ void k_split(const float* __restrict__ in, bf16* __restrict__ hi,
                        bf16* __restrict__ lo, int n) {
    int i = blockIdx.x * blockDim.x + threadIdx.x;
    if (i < n) {
        float f = in[i];
        bf16 h = __float2bfloat16(f);
        hi[i] = h;
        lo[i] = __float2bfloat16(f - __bfloat162float(h));
    }
}
__global__ void k_splitT(const float* __restrict__ in, bf16* __restrict__ hi,
                         bf16* __restrict__ lo, int K, int N) {
    int i = blockIdx.x * blockDim.x + threadIdx.x;
    if (i < K * N) {
        int n = i / K, k = i % K;
        float f = in[(size_t)k * N + n];
        bf16 h = __float2bfloat16(f);
        hi[i] = h;
        lo[i] = __float2bfloat16(f - __bfloat162float(h));
    }
}

// ---------------- bf16x3 GEMM via mma.sync ----------------------------------
// MODE 0: scatter into q/k/v (hi/lo) per-head layout [bh][s][d]
// MODE 1: fp32 out + bias.
template <int MODE>
__global__ void __launch_bounds__(256, 1)
gemm_mma(const bf16* __restrict__ Ahi, const bf16* __restrict__ Alo,
         const bf16* __restrict__ Bhi, const bf16* __restrict__ Blo,
         int Kd,
         bf16* __restrict__ qhi, bf16* __restrict__ qlo,
         bf16* __restrict__ khi, bf16* __restrict__ klo,
         bf16* __restrict__ vhi, bf16* __restrict__ vlo,
         const float* __restrict__ bias, float* __restrict__ outp) {
    extern __shared__ char smc[];
    const uint32_t sb = smem_u32(smc);
    const int tid = threadIdx.x, w = tid >> 5, lane = tid & 31;
    const int m0 = blockIdx.y * 128, n0 = blockIdx.x * 128;
    const int wm = w & 3, wn = w >> 2;
    const uint32_t STG = 65536;

    float acc[2][8][4] = {};

    auto issue = [&](int kc, int stg) {
        uint32_t base = sb + (uint32_t)stg * STG;
#pragma unroll
        for (int i = tid; i < 1024; i += 256) {
            int r = i >> 3, c = i & 7;
            uint32_t off = swz(r, c);
            size_t ga = (size_t)(m0 + r) * Kd + kc + c * 8;
            size_t gb = (size_t)(n0 + r) * Kd + kc + c * 8;
            cp16(base + off,          Ahi + ga);
            cp16(base + 16384 + off,  Alo + ga);
            cp16(base + 32768 + off,  Bhi + gb);
            cp16(base + 49152 + off,  Blo + gb);
        }
    };

    const int nch = Kd / 64;
    issue(0, 0); CP_COMMIT();

    for (int kc = 0; kc < nch; kc++) {
        if (kc + 1 < nch) issue((kc + 1) * 64, (kc + 1) & 1);
        CP_COMMIT();
        CP_WAIT1();
        __syncthreads();

        const uint32_t As = sb + (uint32_t)(kc & 1) * STG;
        const uint32_t Bs = As + 32768;
#pragma unroll
        for (int combo = 0; combo < 3; combo++) {
            const uint32_t Ab = As + ((combo == 2) ? 16384u : 0u);
            const uint32_t Bb = Bs + ((combo == 1) ? 16384u : 0u);
#pragma unroll
            for (int ks = 0; ks < 4; ks++) {
                uint32_t af[2][4];
#pragma unroll
                for (int mt = 0; mt < 2; mt++) {
                    int rr = 32 * wm + 16 * mt + (lane & 7) + ((lane >> 3) & 1) * 8;
                    int cc = 2 * ks + (lane >> 4);
                    ldsm4(af[mt][0], af[mt][1], af[mt][2], af[mt][3], Ab + swz(rr, cc));
                }
#pragma unroll
                for (int ntp = 0; ntp < 4; ntp++) {
                    uint32_t b0, b1, b2, b3;
                    int rr = 64 * wn + 16 * ntp + (lane & 7) + ((lane >> 4) ? 8 : 0);
                    int cc = 2 * ks + ((lane >> 3) & 1);
                    ldsm4(b0, b1, b2, b3, Bb + swz(rr, cc));
#pragma unroll
                    for (int mt = 0; mt < 2; mt++) {
                        mma_bf16(acc[mt][2 * ntp],     af[mt], b0, b1);
                        mma_bf16(acc[mt][2 * ntp + 1], af[mt], b2, b3);
                    }
                }
            }
        }
        __syncthreads();
    }

    // epilogue
#pragma unroll
    for (int mt = 0; mt < 2; mt++) {
#pragma unroll
        for (int i = 0; i < 2; i++) {
            const int gm = m0 + 32 * wm + 16 * mt + (lane >> 2) + i * 8;
#pragma unroll
            for (int nt = 0; nt < 8; nt++) {
                const int gn = n0 + 64 * wn + 8 * nt + 2 * (lane & 3);
                float v0 = acc[mt][nt][2 * i], v1 = acc[mt][nt][2 * i + 1];
                if (MODE == 0) {
                    const int seg = gn >> 9, nn = gn & 511;
                    const int h = nn >> 6, d = nn & 63;
                    const int bI = gm >> 11, s = gm & 2047;
                    size_t idx = ((size_t)((bI * 8 + h) * 2048 + s)) * 64 + d;
                    uint32_t ph, pl;
                    split2(v0, v1, ph, pl);
                    bf16* dh = (seg == 0) ? qhi : (seg == 1) ? khi : vhi;
                    bf16* dl = (seg == 0) ? qlo : (seg == 1) ? klo : vlo;
                    *reinterpret_cast<uint32_t*>(dh + idx) = ph;
                    *reinterpret_cast<uint32_t*>(dl + idx) = pl;
                } else {
                    float2 o = make_float2(v0 + bias[gn], v1 + bias[gn + 1]);
                    *reinterpret_cast<float2*>(outp + (size_t)gm * 512 + gn) = o;
                }
            }
        }
    }
}

// ---------------- attention: HMMA flash, q/k/P/V all hi-lo ------------------
__global__ void __launch_bounds__(256, 1)
attn_mma(const bf16* __restrict__ qhig, const bf16* __restrict__ qlog,
         const bf16* __restrict__ khig, const bf16* __restrict__ klog,
         const bf16* __restrict__ vhig, const bf16* __restrict__ vlog,
         const float* __restrict__ log_temp,
         bf16* __restrict__ ahi, bf16* __restrict__ alo) {
    extern __shared__ char smc[];
    const uint32_t sb = smem_u32(smc);
    const int tid = threadIdx.x, w = tid >> 5, lane = tid & 31;
    const int q0 = blockIdx.x * 128;
    const int bh = blockIdx.y, b = bh >> 3, h = bh & 7;
    // stage layout: Khi | Klo | Vhi | Vlo (16K each)
    const uint32_t KH = 0, KL = 16384, VH = 32768, VL = 49152, STG = 65536;
    const uint32_t QH = 131072, QL = 147456;

    const float scale = __expf(*log_temp);
    const size_t bho = (size_t)bh * 2048 * 64;

    // Q hi/lo -> smem
#pragma unroll
    for (int i = tid; i < 1024; i += 256) {
        int r = i >> 3, c = i & 7;
        uint32_t off = swz(r, c);
        *reinterpret_cast<uint4*>(smc + QH + off) =
            *reinterpret_cast<const uint4*>(qhig + bho + (size_t)(q0 + r) * 64 + c * 8);
        *reinterpret_cast<uint4*>(smc + QL + off) =
            *reinterpret_cast<const uint4*>(qlog + bho + (size_t)(q0 + r) * 64 + c * 8);
    }

    auto issue = [&](int t, int stg) {
        const size_t o = bho + (size_t)t * 128 * 64;
        uint32_t base = sb + (uint32_t)stg * STG;
#pragma unroll
        for (int i = tid; i < 1024; i += 256) {
            int r = i >> 3, c = i & 7;
            uint32_t off = swz(r, c);
            size_t g = o + (size_t)r * 64 + c * 8;
            cp16(base + KH + off, khig + g);
            cp16(base + KL + off, klog + g);
            cp16(base + VH + off, vhig + g);
            cp16(base + VL + off, vlog + g);
        }
    };
    issue(0, 0); CP_COMMIT();
    __syncthreads();   // Q visible

    // Q fragments hi/lo (persist in registers)
    uint32_t aqh[4][4], aql[4][4];
    {
        int rr = 16 * w + (lane & 7) + ((lane >> 3) & 1) * 8;
#pragma unroll
        for (int ks = 0; ks < 4; ks++) {
            int cc = 2 * ks + (lane >> 4);
            ldsm4(aqh[ks][0], aqh[ks][1], aqh[ks][2], aqh[ks][3], sb + QH + swz(rr, cc));
            ldsm4(aql[ks][0], aql[ks][1], aql[ks][2], aql[ks][3], sb + QL + swz(rr, cc));
        }
    }

    float O[8][4] = {};
    float l0 = 0.f, l1 = 0.f;
    const int rg = 16 * w + (lane >> 2);
    const int qi0 = q0 + rg, qi1 = qi0 + 8;

    for (int t = 0; t < 16; t++) {
        if (t + 1 < 16) issue(t + 1, (t + 1) & 1);
        CP_COMMIT();
        CP_WAIT1();
        __syncthreads();

        const uint32_t stgb = sb + (uint32_t)(t & 1) * STG;
        const uint32_t Kh = stgb + KH, Kl = stgb + KL;
        const uint32_t Vh = stgb + VH, Vl = stgb + VL;

        // S = (qh+ql) @ (kh+kl)^T  (drop ql*kl)
        float S[16][4] = {};
#pragma unroll
        for (int ks = 0; ks < 4; ks++) {
#pragma unroll
            for (int ntp = 0; ntp < 8; ntp++) {
                int rr = 16 * ntp + (lane & 7) + ((lane >> 4) ? 8 : 0);
                int cc = 2 * ks + ((lane >> 3) & 1);
                uint32_t bh0, bh1, bh2, bh3, bl0, bl1, bl2, bl3;
                ldsm4(bh0, bh1, bh2, bh3, Kh + swz(rr, cc));
                ldsm4(bl0, bl1, bl2, bl3, Kl + swz(rr, cc));
                mma_bf16(S[2 * ntp],     aqh[ks], bh0, bh1);
                mma_bf16(S[2 * ntp + 1], aqh[ks], bh2, bh3);
                mma_bf16(S[2 * ntp],     aqh[ks], bl0, bl1);
                mma_bf16(S[2 * ntp + 1], aqh[ks], bl2, bl3);
                mma_bf16(S[2 * ntp],     aql[ks], bh0, bh1);
                mma_bf16(S[2 * ntp + 1], aql[ks], bh2, bh3);
            }
        }

        // exp + diag mask (keep e in fp32 in S)
        const int j00 = t * 128 + 2 * (lane & 3);
#pragma unroll
        for (int nt = 0; nt < 16; nt++) {
            int jc = j00 + 8 * nt;
            float e0 = (jc     == qi0) ? 0.f : __expf(S[nt][0] * scale);
            float e1 = (jc + 1 == qi0) ? 0.f : __expf(S[nt][1] * scale);
            float e2 = (jc     == qi1) ? 0.f : __expf(S[nt][2] * scale);
            float e3 = (jc + 1 == qi1) ? 0.f : __expf(S[nt][3] * scale);
            l0 += e0 + e1;
            l1 += e2 + e3;
            S[nt][0] = e0; S[nt][1] = e1; S[nt][2] = e2; S[nt][3] = e3;
        }

        // O += Ph@Vh + Ph@Vl + Pl@Vh   (P split just-in-time)
#pragma unroll
        for (int ks = 0; ks < 8; ks++) {
            uint32_t aph[4], apl[4];
            split2(S[2 * ks][0],     S[2 * ks][1],     aph[0], apl[0]);
            split2(S[2 * ks][2],     S[2 * ks][3],     aph[1], apl[1]);
            split2(S[2 * ks + 1][0], S[2 * ks + 1][1], aph[2], apl[2]);
            split2(S[2 * ks + 1][2], S[2 * ks + 1][3], aph[3], apl[3]);
#pragma unroll
            for (int ntp = 0; ntp < 4; ntp++) {
                int rr = 16 * ks + (lane & 7) + ((lane >> 3) & 1) * 8;
                int cc = 2 * ntp + (lane >> 4);
                uint32_t h0, h1, h2, h3, L0, L1, L2, L3;
                ldsm4t(h0, h1, h2, h3, Vh + swz(rr, cc));
                ldsm4t(L0, L1, L2, L3, Vl + swz(rr, cc));
                mma_bf16(O[2 * ntp],     aph, h0, h1);
                mma_bf16(O[2 * ntp + 1], aph, h2, h3);
                mma_bf16(O[2 * ntp],     aph, L0, L1);
                mma_bf16(O[2 * ntp + 1], aph, L2, L3);
                mma_bf16(O[2 * ntp],     apl, h0, h1);
                mma_bf16(O[2 * ntp + 1], apl, h2, h3);
            }
        }
        __syncthreads();
    }

    l0 += __shfl_xor_sync(0xffffffffu, l0, 1);
    l0 += __shfl_xor_sync(0xffffffffu, l0, 2);
    l1 += __shfl_xor_sync(0xffffffffu, l1, 1);
    l1 += __shfl_xor_sync(0xffffffffu, l1, 2);
    const float inv0 = 1.f / l0, inv1 = 1.f / l1;

#pragma unroll
    for (int i = 0; i < 2; i++) {
        const float inv = i ? inv1 : inv0;
        const size_t gm = (size_t)(b * 2048 + q0 + rg + i * 8);
#pragma unroll
        for (int nt = 0; nt < 8; nt++) {
            const int d = 8 * nt + 2 * (lane & 3);
            uint32_t ph, pl;
            split2(O[nt][2 * i] * inv, O[nt][2 * i + 1] * inv, ph, pl);
            size_t idx = gm * INNER + h * DHEAD + d;
            *reinterpret_cast<uint32_t*>(ahi + idx) = ph;
            *reinterpret_cast<uint32_t*>(alo + idx) = pl;
        }
    }
}

// ---------------- launch -----------------------------------------------------
extern "C" void kernel_launch(void* const* d_in, const int* in_sizes, int n_in,
                              void* d_out, int out_size) {
    const float* x        = (const float*)d_in[0];
    const float* W_qkv    = (const float*)d_in[1];
    const float* log_temp = (const float*)d_in[2];
    const float* W_out    = (const float*)d_in[3];
    const float* b_out    = (const float*)d_in[4];
    float* out = (float*)d_out;

    bf16 *xhi, *xlo, *wqh, *wql, *woh, *wol;
    bf16 *qh, *ql, *kh, *kl, *vh, *vl, *ah, *al;
    cudaGetSymbolAddress((void**)&xhi, g_xhi);    cudaGetSymbolAddress((void**)&xlo, g_xlo);
    cudaGetSymbolAddress((void**)&wqh, g_wqT_hi); cudaGetSymbolAddress((void**)&wql, g_wqT_lo);
    cudaGetSymbolAddress((void**)&woh, g_woT_hi); cudaGetSymbolAddress((void**)&wol, g_woT_lo);
    cudaGetSymbolAddress((void**)&qh, g_qhi);     cudaGetSymbolAddress((void**)&ql, g_qlo);
    cudaGetSymbolAddress((void**)&kh, g_khi);     cudaGetSymbolAddress((void**)&kl, g_klo);
    cudaGetSymbolAddress((void**)&vh, g_vhi);     cudaGetSymbolAddress((void**)&vl, g_vlo);
    cudaGetSymbolAddress((void**)&ah, g_ahi);     cudaGetSymbolAddress((void**)&al, g_alo);

    const int GSM = 131072;
    const int ASM = 163840;
    cudaFuncSetAttribute(gemm_mma<0>, cudaFuncAttributeMaxDynamicSharedMemorySize, GSM);
    cudaFuncSetAttribute(gemm_mma<1>, cudaFuncAttributeMaxDynamicSharedMemorySize, GSM);
    cudaFuncSetAttribute(attn_mma,    cudaFuncAttributeMaxDynamicSharedMemorySize, ASM);

    k_split<<<(NROWS * DIMX + 255) / 256, 256>>>(x, xhi, xlo, NROWS * DIMX);
    k_splitT<<<(DIMX * 3 * INNER + 255) / 256, 256>>>(W_qkv, wqh, wql, DIMX, 3 * INNER);
    k_splitT<<<(INNER * DIMX + 255) / 256, 256>>>(W_out, woh, wol, INNER, DIMX);

    // 1) QKV projection (bf16x3) -> q/k/v hi-lo per-head layout
    gemm_mma<0><<<dim3(12, 64), 256, GSM>>>(xhi, xlo, wqh, wql, DIMX,
                                            qh, ql, kh, kl, vh, vl, nullptr, nullptr);
    // 2) attention (all paths error-compensated)
    attn_mma<<<dim3(SSEQ / 128, BB * HEADS), 256, ASM>>>(qh, ql, kh, kl, vh, vl,
                                                         log_temp, ah, al);
    // 3) output projection (bf16x3) + bias -> fp32
    gemm_mma<1><<<dim3(4, 64), 256, GSM>>>(ah, al, woh, wol, INNER,
                                           nullptr, nullptr, nullptr, nullptr,
                                           nullptr, nullptr, b_out, out);
}

// round 6
// speedup vs baseline: 5.4781x; 1.5356x over previous
#include <cuda_runtime.h>
#include <cuda_bf16.h>
#include <cuda_fp16.h>
#include <cstdint>
#include <math.h>

typedef __nv_bfloat16 bf16;

#define BB 4
#define SSEQ 2048
#define DIMX 512
#define HEADS 8
#define DHEAD 64
#define INNER 512
#define NROWS (BB * SSEQ)   // 8192

// ---------------- device scratch -------------------------------------------
__device__ bf16 g_xhi[NROWS * DIMX],        g_xlo[NROWS * DIMX];
__device__ bf16 g_wqT_hi[3 * INNER * DIMX], g_wqT_lo[3 * INNER * DIMX];
__device__ bf16 g_woT_hi[DIMX * INNER],     g_woT_lo[DIMX * INNER];
__device__ __half g_q[NROWS * INNER];   // [bh][s][64] fp16
__device__ __half g_k[NROWS * INNER];
__device__ __half g_v[NROWS * INNER];
__device__ bf16 g_ahi[NROWS * INNER], g_alo[NROWS * INNER];  // [b*s][512]

// ---------------- helpers ---------------------------------------------------
__device__ __forceinline__ uint32_t smem_u32(const void* p) {
    uint32_t a;
    asm("{ .reg .u64 t; cvta.to.shared.u64 t, %1; cvt.u32.u64 %0, t; }" : "=r"(a) : "l"(p));
    return a;
}
__device__ __forceinline__ void ldsm4(uint32_t& r0, uint32_t& r1, uint32_t& r2,
                                      uint32_t& r3, uint32_t addr) {
    asm volatile("ldmatrix.sync.aligned.m8n8.x4.shared.b16 {%0,%1,%2,%3}, [%4];"
                 : "=r"(r0), "=r"(r1), "=r"(r2), "=r"(r3) : "r"(addr));
}
__device__ __forceinline__ void ldsm4t(uint32_t& r0, uint32_t& r1, uint32_t& r2,
                                       uint32_t& r3, uint32_t addr) {
    asm volatile("ldmatrix.sync.aligned.m8n8.x4.trans.shared.b16 {%0,%1,%2,%3}, [%4];"
                 : "=r"(r0), "=r"(r1), "=r"(r2), "=r"(r3) : "r"(addr));
}
__device__ __forceinline__ void mma_bf16(float* c, const uint32_t a[4],
                                         uint32_t b0, uint32_t b1) {
    asm volatile(
        "mma.sync.aligned.m16n8k16.row.col.f32.bf16.bf16.f32 "
        "{%0,%1,%2,%3}, {%4,%5,%6,%7}, {%8,%9}, {%0,%1,%2,%3};"
        : "+f"(c[0]), "+f"(c[1]), "+f"(c[2]), "+f"(c[3])
        : "r"(a[0]), "r"(a[1]), "r"(a[2]), "r"(a[3]), "r"(b0), "r"(b1));
}
__device__ __forceinline__ void mma_f16(float* c, const uint32_t a[4],
                                        uint32_t b0, uint32_t b1) {
    asm volatile(
        "mma.sync.aligned.m16n8k16.row.col.f32.f16.f16.f32 "
        "{%0,%1,%2,%3}, {%4,%5,%6,%7}, {%8,%9}, {%0,%1,%2,%3};"
        : "+f"(c[0]), "+f"(c[1]), "+f"(c[2]), "+f"(c[3])
        : "r"(a[0]), "r"(a[1]), "r"(a[2]), "r"(a[3]), "r"(b0), "r"(b1));
}
__device__ __forceinline__ void cp16(uint32_t dst, const void* src) {
    asm volatile("cp.async.cg.shared.global [%0], [%1], 16;" :: "r"(dst), "l"(src));
}
#define CP_COMMIT() asm volatile("cp.async.commit_group;" ::: "memory")
#define CP_WAIT1()  asm volatile("cp.async.wait_group 1;" ::: "memory")
#define CP_WAIT2()  asm volatile("cp.async.wait_group 2;" ::: "memory")

__device__ __forceinline__ uint32_t pk2(bf16 a, bf16 b) {
    return (uint32_t)__bfloat16_as_ushort(a) | ((uint32_t)__bfloat16_as_ushort(b) << 16);
}
__device__ __forceinline__ void split2(float e0, float e1, uint32_t& h, uint32_t& l) {
    bf16 h0 = __float2bfloat16(e0);
    bf16 h1 = __float2bfloat16(e1);
    bf16 l0 = __float2bfloat16(e0 - __bfloat162float(h0));
    bf16 l1 = __float2bfloat16(e1 - __bfloat162float(h1));
    h = pk2(h0, h1);
    l = pk2(l0, l1);
}
__device__ __forceinline__ uint32_t pkh(float a, float b) {   // a in low half
    __half2 x = __floats2half2_rn(a, b);
    return *reinterpret_cast<uint32_t*>(&x);
}
// 16B-chunk swizzle within 128B rows (conflict-free ldmatrix)
__device__ __forceinline__ uint32_t swz(int r, int c) {
    return (uint32_t)r * 128u + (uint32_t)((c ^ (r & 7)) & 7) * 16u;
}

// ---------------- convert kernels -------------------------------------------
__global__ void k_split(const float* __restrict__ in, bf16* __restrict__ hi,
                        bf16* __restrict__ lo, int n) {
    int i = blockIdx.x * blockDim.x + threadIdx.x;
    if (i < n) {
        float f = in[i];
        bf16 h = __float2bfloat16(f);
        hi[i] = h;
        lo[i] = __float2bfloat16(f - __bfloat162float(h));
    }
}
__global__ void k_splitT(const float* __restrict__ in, bf16* __restrict__ hi,
                         bf16* __restrict__ lo, int K, int N) {
    int i = blockIdx.x * blockDim.x + threadIdx.x;
    if (i < K * N) {
        int n = i / K, k = i % K;
        float f = in[(size_t)k * N + n];
        bf16 h = __float2bfloat16(f);
        hi[i] = h;
        lo[i] = __float2bfloat16(f - __bfloat162float(h));
    }
}

// ---------------- bf16x3 GEMM via mma.sync, 512 threads ---------------------
// tile 128x128, warp grid 4x4, warp tile 32x32.
// MODE 0: write q/k/v fp16 per-head layout [bh][s][d];  MODE 1: fp32 + bias.
template <int MODE>
__global__ void __launch_bounds__(512, 1)
gemm_mma(const bf16* __restrict__ Ahi, const bf16* __restrict__ Alo,
         const bf16* __restrict__ Bhi, const bf16* __restrict__ Blo,
         int Kd,
         __half* __restrict__ q, __half* __restrict__ k, __half* __restrict__ v,
         const float* __restrict__ bias, float* __restrict__ outp) {
    extern __shared__ char smc[];
    const uint32_t sb = smem_u32(smc);
    const int tid = threadIdx.x, w = tid >> 5, lane = tid & 31;
    const int m0 = blockIdx.y * 128, n0 = blockIdx.x * 128;
    const int wm = w & 3, wn = w >> 2;
    const uint32_t STG = 65536;

    float acc[2][4][4] = {};

    auto issue = [&](int kc, int stg) {
        uint32_t base = sb + (uint32_t)stg * STG;
#pragma unroll
        for (int i = tid; i < 1024; i += 512) {
            int r = i >> 3, c = i & 7;
            uint32_t off = swz(r, c);
            size_t ga = (size_t)(m0 + r) * Kd + kc + c * 8;
            size_t gb = (size_t)(n0 + r) * Kd + kc + c * 8;
            cp16(base + off,          Ahi + ga);
            cp16(base + 16384 + off,  Alo + ga);
            cp16(base + 32768 + off,  Bhi + gb);
            cp16(base + 49152 + off,  Blo + gb);
        }
    };

    const int nch = Kd / 64;
    issue(0, 0); CP_COMMIT();

    for (int kc = 0; kc < nch; kc++) {
        if (kc + 1 < nch) issue((kc + 1) * 64, (kc + 1) & 1);
        CP_COMMIT();
        CP_WAIT1();
        __syncthreads();

        const uint32_t As = sb + (uint32_t)(kc & 1) * STG;
        const uint32_t Bs = As + 32768;
#pragma unroll
        for (int combo = 0; combo < 3; combo++) {
            const uint32_t Ab = As + ((combo == 2) ? 16384u : 0u);
            const uint32_t Bb = Bs + ((combo == 1) ? 16384u : 0u);
#pragma unroll
            for (int ks = 0; ks < 4; ks++) {
                uint32_t af[2][4];
#pragma unroll
                for (int mt = 0; mt < 2; mt++) {
                    int rr = 32 * wm + 16 * mt + (lane & 7) + ((lane >> 3) & 1) * 8;
                    int cc = 2 * ks + (lane >> 4);
                    ldsm4(af[mt][0], af[mt][1], af[mt][2], af[mt][3], Ab + swz(rr, cc));
                }
#pragma unroll
                for (int ntp = 0; ntp < 2; ntp++) {
                    uint32_t b0, b1, b2, b3;
                    int rr = 32 * wn + 16 * ntp + (lane & 7) + ((lane >> 4) ? 8 : 0);
                    int cc = 2 * ks + ((lane >> 3) & 1);
                    ldsm4(b0, b1, b2, b3, Bb + swz(rr, cc));
#pragma unroll
                    for (int mt = 0; mt < 2; mt++) {
                        mma_bf16(acc[mt][2 * ntp],     af[mt], b0, b1);
                        mma_bf16(acc[mt][2 * ntp + 1], af[mt], b2, b3);
                    }
                }
            }
        }
        __syncthreads();
    }

    // epilogue
#pragma unroll
    for (int mt = 0; mt < 2; mt++) {
#pragma unroll
        for (int i = 0; i < 2; i++) {
            const int gm = m0 + 32 * wm + 16 * mt + (lane >> 2) + i * 8;
#pragma unroll
            for (int nt = 0; nt < 4; nt++) {
                const int gn = n0 + 32 * wn + 8 * nt + 2 * (lane & 3);
                float v0 = acc[mt][nt][2 * i], v1 = acc[mt][nt][2 * i + 1];
                if (MODE == 0) {
                    const int seg = gn >> 9, nn = gn & 511;
                    const int h = nn >> 6, d = nn & 63;
                    const int bI = gm >> 11, s = gm & 2047;
                    size_t idx = ((size_t)((bI * 8 + h) * 2048 + s)) * 64 + d;
                    __half* dst = (seg == 0) ? q : (seg == 1) ? k : v;
                    *reinterpret_cast<uint32_t*>(dst + idx) = pkh(v0, v1);
                } else {
                    float2 o = make_float2(v0 + bias[gn], v1 + bias[gn + 1]);
                    *reinterpret_cast<float2*>(outp + (size_t)gm * 512 + gn) = o;
                }
            }
        }
    }
}

// ---------------- attention: single-fp16 HMMA flash, 3-stage pipeline -------
__global__ void __launch_bounds__(256, 1)
attn_mma(const __half* __restrict__ qg, const __half* __restrict__ kg,
         const __half* __restrict__ vg, const float* __restrict__ log_temp,
         bf16* __restrict__ ahi, bf16* __restrict__ alo) {
    extern __shared__ char smc[];
    const uint32_t sb = smem_u32(smc);
    const int tid = threadIdx.x, w = tid >> 5, lane = tid & 31;
    const int q0 = blockIdx.x * 128;
    const int bh = blockIdx.y, b = bh >> 3, h = bh & 7;
    // 3 stages: K 16K + V 16K each; Q at 98304
    const uint32_t KO = 0, VO = 16384, STG = 32768, QO = 98304;

    const float scale = __expf(*log_temp);
    const size_t bho = (size_t)bh * 2048 * 64;

    // Q -> smem (plain stores)
#pragma unroll
    for (int i = tid; i < 1024; i += 256) {
        int r = i >> 3, c = i & 7;
        *reinterpret_cast<uint4*>(smc + QO + swz(r, c)) =
            *reinterpret_cast<const uint4*>(qg + bho + (size_t)(q0 + r) * 64 + c * 8);
    }

    auto issue = [&](int t, int stg) {
        const size_t o = bho + (size_t)t * 128 * 64;
        uint32_t base = sb + (uint32_t)stg * STG;
#pragma unroll
        for (int i = tid; i < 1024; i += 256) {
            int r = i >> 3, c = i & 7;
            uint32_t off = swz(r, c);
            size_t g = o + (size_t)r * 64 + c * 8;
            cp16(base + KO + off, kg + g);
            cp16(base + VO + off, vg + g);
        }
    };
    issue(0, 0); CP_COMMIT();
    issue(1, 1); CP_COMMIT();
    __syncthreads();   // Q visible

    // Q fragments (persist)
    uint32_t aq[4][4];
    {
        int rr = 16 * w + (lane & 7) + ((lane >> 3) & 1) * 8;
#pragma unroll
        for (int ks = 0; ks < 4; ks++) {
            int cc = 2 * ks + (lane >> 4);
            ldsm4(aq[ks][0], aq[ks][1], aq[ks][2], aq[ks][3], sb + QO + swz(rr, cc));
        }
    }

    float O[8][4] = {};
    float l0 = 0.f, l1 = 0.f;
    const int rg = 16 * w + (lane >> 2);
    const int qi0 = q0 + rg, qi1 = qi0 + 8;

    for (int t = 0; t < 16; t++) {
        if (t + 2 < 16) {
            int nt_ = t + 2;
            int s3 = nt_ - (nt_ >= 3 ? 3 : 0) - (nt_ >= 6 ? 3 : 0) - (nt_ >= 9 ? 3 : 0)
                   - (nt_ >= 12 ? 3 : 0) - (nt_ >= 15 ? 3 : 0);
            issue(nt_, s3);
        }
        CP_COMMIT();
        CP_WAIT2();
        __syncthreads();

        int ts = t - (t >= 3 ? 3 : 0) - (t >= 6 ? 3 : 0) - (t >= 9 ? 3 : 0)
               - (t >= 12 ? 3 : 0) - (t >= 15 ? 3 : 0);
        const uint32_t stgb = sb + (uint32_t)ts * STG;
        const uint32_t Ks = stgb + KO, Vs = stgb + VO;

        // S = Q @ K^T
        float S[16][4] = {};
#pragma unroll
        for (int ks = 0; ks < 4; ks++) {
#pragma unroll
            for (int ntp = 0; ntp < 8; ntp++) {
                uint32_t b0, b1, b2, b3;
                int rr = 16 * ntp + (lane & 7) + ((lane >> 4) ? 8 : 0);
                int cc = 2 * ks + ((lane >> 3) & 1);
                ldsm4(b0, b1, b2, b3, Ks + swz(rr, cc));
                mma_f16(S[2 * ntp],     aq[ks], b0, b1);
                mma_f16(S[2 * ntp + 1], aq[ks], b2, b3);
            }
        }

        // exp + diag mask, pack P to fp16
        const int j00 = t * 128 + 2 * (lane & 3);
        uint32_t ep[16][2];
#pragma unroll
        for (int nt = 0; nt < 16; nt++) {
            int jc = j00 + 8 * nt;
            float e0 = (jc     == qi0) ? 0.f : __expf(S[nt][0] * scale);
            float e1 = (jc + 1 == qi0) ? 0.f : __expf(S[nt][1] * scale);
            float e2 = (jc     == qi1) ? 0.f : __expf(S[nt][2] * scale);
            float e3 = (jc + 1 == qi1) ? 0.f : __expf(S[nt][3] * scale);
            l0 += e0 + e1;
            l1 += e2 + e3;
            ep[nt][0] = pkh(e0, e1);
            ep[nt][1] = pkh(e2, e3);
        }

        // O += P @ V
#pragma unroll
        for (int ks = 0; ks < 8; ks++) {
            uint32_t ap[4] = { ep[2 * ks][0], ep[2 * ks][1],
                               ep[2 * ks + 1][0], ep[2 * ks + 1][1] };
#pragma unroll
            for (int ntp = 0; ntp < 4; ntp++) {
                uint32_t b0, b1, b2, b3;
                int rr = 16 * ks + (lane & 7) + ((lane >> 3) & 1) * 8;
                int cc = 2 * ntp + (lane >> 4);
                ldsm4t(b0, b1, b2, b3, Vs + swz(rr, cc));
                mma_f16(O[2 * ntp],     ap, b0, b1);
                mma_f16(O[2 * ntp + 1], ap, b2, b3);
            }
        }
        __syncthreads();
    }

    l0 += __shfl_xor_sync(0xffffffffu, l0, 1);
    l0 += __shfl_xor_sync(0xffffffffu, l0, 2);
    l1 += __shfl_xor_sync(0xffffffffu, l1, 1);
    l1 += __shfl_xor_sync(0xffffffffu, l1, 2);
    const float inv0 = 1.f / l0, inv1 = 1.f / l1;

#pragma unroll
    for (int i = 0; i < 2; i++) {
        const float inv = i ? inv1 : inv0;
        const size_t gm = (size_t)(b * 2048 + q0 + rg + i * 8);
#pragma unroll
        for (int nt = 0; nt < 8; nt++) {
            const int d = 8 * nt + 2 * (lane & 3);
            uint32_t ph, pl;
            split2(O[nt][2 * i] * inv, O[nt][2 * i + 1] * inv, ph, pl);
            size_t idx = gm * INNER + h * DHEAD + d;
            *reinterpret_cast<uint32_t*>(ahi + idx) = ph;
            *reinterpret_cast<uint32_t*>(alo + idx) = pl;
        }
    }
}

// ---------------- launch -----------------------------------------------------
extern "C" void kernel_launch(void* const* d_in, const int* in_sizes, int n_in,
                              void* d_out, int out_size) {
    const float* x        = (const float*)d_in[0];
    const float* W_qkv    = (const float*)d_in[1];
    const float* log_temp = (const float*)d_in[2];
    const float* W_out    = (const float*)d_in[3];
    const float* b_out    = (const float*)d_in[4];
    float* out = (float*)d_out;

    bf16 *xhi, *xlo, *wqh, *wql, *woh, *wol, *ah, *al;
    __half *q, *k, *v;
    cudaGetSymbolAddress((void**)&xhi, g_xhi);    cudaGetSymbolAddress((void**)&xlo, g_xlo);
    cudaGetSymbolAddress((void**)&wqh, g_wqT_hi); cudaGetSymbolAddress((void**)&wql, g_wqT_lo);
    cudaGetSymbolAddress((void**)&woh, g_woT_hi); cudaGetSymbolAddress((void**)&wol, g_woT_lo);
    cudaGetSymbolAddress((void**)&q, g_q);
    cudaGetSymbolAddress((void**)&k, g_k);
    cudaGetSymbolAddress((void**)&v, g_v);
    cudaGetSymbolAddress((void**)&ah, g_ahi);     cudaGetSymbolAddress((void**)&al, g_alo);

    const int GSM = 131072;
    const int ASM = 114688;
    cudaFuncSetAttribute(gemm_mma<0>, cudaFuncAttributeMaxDynamicSharedMemorySize, GSM);
    cudaFuncSetAttribute(gemm_mma<1>, cudaFuncAttributeMaxDynamicSharedMemorySize, GSM);
    cudaFuncSetAttribute(attn_mma,    cudaFuncAttributeMaxDynamicSharedMemorySize, ASM);

    k_split<<<(NROWS * DIMX + 255) / 256, 256>>>(x, xhi, xlo, NROWS * DIMX);
    k_splitT<<<(DIMX * 3 * INNER + 255) / 256, 256>>>(W_qkv, wqh, wql, DIMX, 3 * INNER);
    k_splitT<<<(INNER * DIMX + 255) / 256, 256>>>(W_out, woh, wol, INNER, DIMX);

    // 1) QKV projection (bf16x3, 512 thr) -> q/k/v fp16 per-head layout
    gemm_mma<0><<<dim3(12, 64), 512, GSM>>>(xhi, xlo, wqh, wql, DIMX,
                                            q, k, v, nullptr, nullptr);
    // 2) attention (single fp16, 3-stage pipeline)
    attn_mma<<<dim3(SSEQ / 128, BB * HEADS), 256, ASM>>>(q, k, v, log_temp, ah, al);
    // 3) output projection (bf16x3, 512 thr) + bias -> fp32
    gemm_mma<1><<<dim3(4, 64), 512, GSM>>>(ah, al, woh, wol, INNER,
                                           nullptr, nullptr, nullptr, b_out, out);
}

// round 7
// speedup vs baseline: 6.9026x; 1.2600x over previous
#include <cuda_runtime.h>
#include <cuda_fp16.h>
#include <cstdint>
#include <math.h>

#define BB 4
#define SSEQ 2048
#define DIMX 512
#define HEADS 8
#define DHEAD 64
#define INNER 512
#define NROWS (BB * SSEQ)   // 8192

// ---------------- device scratch (all fp16 hi/lo) ---------------------------
__device__ __half g_xh[NROWS * DIMX],        g_xl[NROWS * DIMX];
__device__ __half g_wqh[3 * INNER * DIMX],   g_wql[3 * INNER * DIMX];
__device__ __half g_woh[DIMX * INNER];
__device__ __half g_q[NROWS * INNER];   // [bh][s][64]
__device__ __half g_k[NROWS * INNER];
__device__ __half g_v[NROWS * INNER];
__device__ __half g_a[NROWS * INNER];   // [b*s][512]

// ---------------- helpers ---------------------------------------------------
__device__ __forceinline__ uint32_t smem_u32(const void* p) {
    uint32_t a;
    asm("{ .reg .u64 t; cvta.to.shared.u64 t, %1; cvt.u32.u64 %0, t; }" : "=r"(a) : "l"(p));
    return a;
}
__device__ __forceinline__ void ldsm4(uint32_t& r0, uint32_t& r1, uint32_t& r2,
                                      uint32_t& r3, uint32_t addr) {
    asm volatile("ldmatrix.sync.aligned.m8n8.x4.shared.b16 {%0,%1,%2,%3}, [%4];"
                 : "=r"(r0), "=r"(r1), "=r"(r2), "=r"(r3) : "r"(addr));
}
__device__ __forceinline__ void ldsm4t(uint32_t& r0, uint32_t& r1, uint32_t& r2,
                                       uint32_t& r3, uint32_t addr) {
    asm volatile("ldmatrix.sync.aligned.m8n8.x4.trans.shared.b16 {%0,%1,%2,%3}, [%4];"
                 : "=r"(r0), "=r"(r1), "=r"(r2), "=r"(r3) : "r"(addr));
}
__device__ __forceinline__ void mma_f16(float* c, const uint32_t a[4],
                                        uint32_t b0, uint32_t b1) {
    asm volatile(
        "mma.sync.aligned.m16n8k16.row.col.f32.f16.f16.f32 "
        "{%0,%1,%2,%3}, {%4,%5,%6,%7}, {%8,%9}, {%0,%1,%2,%3};"
        : "+f"(c[0]), "+f"(c[1]), "+f"(c[2]), "+f"(c[3])
        : "r"(a[0]), "r"(a[1]), "r"(a[2]), "r"(a[3]), "r"(b0), "r"(b1));
}
__device__ __forceinline__ void cp16(uint32_t dst, const void* src) {
    asm volatile("cp.async.cg.shared.global [%0], [%1], 16;" :: "r"(dst), "l"(src));
}
#define CP_COMMIT() asm volatile("cp.async.commit_group;" ::: "memory")
#define CP_WAIT1()  asm volatile("cp.async.wait_group 1;" ::: "memory")
#define CP_WAIT2()  asm volatile("cp.async.wait_group 2;" ::: "memory")

__device__ __forceinline__ uint32_t pkh(float a, float b) {   // a in low half
    __half2 x = __floats2half2_rn(a, b);
    return *reinterpret_cast<uint32_t*>(&x);
}
// 16B-chunk swizzle within 128B rows (conflict-free ldmatrix)
__device__ __forceinline__ uint32_t swz(int r, int c) {
    return (uint32_t)r * 128u + (uint32_t)((c ^ (r & 7)) & 7) * 16u;
}

// ---------------- convert kernels (fp16 hi/lo) -------------------------------
__global__ void k_split_h(const float* __restrict__ in, __half* __restrict__ hi,
                          __half* __restrict__ lo, int n) {
    int i = blockIdx.x * blockDim.x + threadIdx.x;
    if (i < n) {
        float f = in[i];
        __half h = __float2half_rn(f);
        hi[i] = h;
        lo[i] = __float2half_rn(f - __half2float(h));
    }
}
template <bool LO>
__global__ void k_splitT_h(const float* __restrict__ in, __half* __restrict__ hi,
                           __half* __restrict__ lo, int K, int N) {
    int i = blockIdx.x * blockDim.x + threadIdx.x;
    if (i < K * N) {
        int n = i / K, k = i % K;
        float f = in[(size_t)k * N + n];
        __half h = __float2half_rn(f);
        hi[i] = h;
        if (LO) lo[i] = __float2half_rn(f - __half2float(h));
    }
}

// ---------------- fp16 multi-term GEMM via mma.sync, 512 threads -------------
// tile 128x128, warp grid 4x4, warp tile 32x32. nterms per block:
// MODE 0 (QKV proj): q/k column-tiles (n0<1024) use 3 terms; V tiles 1 term.
//   epilogue -> q/k/v fp16 per-head layout [bh][s][d]
// MODE 1 (out proj): 1 term, epilogue fp32 + bias.
template <int MODE>
__global__ void __launch_bounds__(512, 1)
gemm_mma(const __half* __restrict__ Ah, const __half* __restrict__ Al,
         const __half* __restrict__ Bh, const __half* __restrict__ Bl,
         int Kd,
         __half* __restrict__ q, __half* __restrict__ k, __half* __restrict__ v,
         const float* __restrict__ bias, float* __restrict__ outp) {
    extern __shared__ char smc[];
    const uint32_t sb = smem_u32(smc);
    const int tid = threadIdx.x, w = tid >> 5, lane = tid & 31;
    const int m0 = blockIdx.y * 128, n0 = blockIdx.x * 128;
    const int wm = w & 3, wn = w >> 2;
    const uint32_t STG = 65536;
    const int nterms = (MODE == 0 && n0 < 1024) ? 3 : 1;

    float acc[2][4][4] = {};

    auto issue = [&](int kc, int stg) {
        uint32_t base = sb + (uint32_t)stg * STG;
#pragma unroll
        for (int i = tid; i < 1024; i += 512) {
            int r = i >> 3, c = i & 7;
            uint32_t off = swz(r, c);
            size_t ga = (size_t)(m0 + r) * Kd + kc + c * 8;
            size_t gb = (size_t)(n0 + r) * Kd + kc + c * 8;
            cp16(base + off,          Ah + ga);
            cp16(base + 32768 + off,  Bh + gb);
            if (nterms == 3) {
                cp16(base + 16384 + off, Al + ga);
                cp16(base + 49152 + off, Bl + gb);
            }
        }
    };

    const int nch = Kd / 64;
    issue(0, 0); CP_COMMIT();

    for (int kc = 0; kc < nch; kc++) {
        if (kc + 1 < nch) issue((kc + 1) * 64, (kc + 1) & 1);
        CP_COMMIT();
        CP_WAIT1();
        __syncthreads();

        const uint32_t As = sb + (uint32_t)(kc & 1) * STG;
        const uint32_t Bs = As + 32768;
#pragma unroll
        for (int combo = 0; combo < 3; combo++) {
            if (combo >= nterms) break;
            const uint32_t Ab = As + ((combo == 2) ? 16384u : 0u);
            const uint32_t Bb = Bs + ((combo == 1) ? 16384u : 0u);
#pragma unroll
            for (int ks = 0; ks < 4; ks++) {
                uint32_t af[2][4];
#pragma unroll
                for (int mt = 0; mt < 2; mt++) {
                    int rr = 32 * wm + 16 * mt + (lane & 7) + ((lane >> 3) & 1) * 8;
                    int cc = 2 * ks + (lane >> 4);
                    ldsm4(af[mt][0], af[mt][1], af[mt][2], af[mt][3], Ab + swz(rr, cc));
                }
#pragma unroll
                for (int ntp = 0; ntp < 2; ntp++) {
                    uint32_t b0, b1, b2, b3;
                    int rr = 32 * wn + 16 * ntp + (lane & 7) + ((lane >> 4) ? 8 : 0);
                    int cc = 2 * ks + ((lane >> 3) & 1);
                    ldsm4(b0, b1, b2, b3, Bb + swz(rr, cc));
#pragma unroll
                    for (int mt = 0; mt < 2; mt++) {
                        mma_f16(acc[mt][2 * ntp],     af[mt], b0, b1);
                        mma_f16(acc[mt][2 * ntp + 1], af[mt], b2, b3);
                    }
                }
            }
        }
        __syncthreads();
    }

    // epilogue
#pragma unroll
    for (int mt = 0; mt < 2; mt++) {
#pragma unroll
        for (int i = 0; i < 2; i++) {
            const int gm = m0 + 32 * wm + 16 * mt + (lane >> 2) + i * 8;
#pragma unroll
            for (int nt = 0; nt < 4; nt++) {
                const int gn = n0 + 32 * wn + 8 * nt + 2 * (lane & 3);
                float v0 = acc[mt][nt][2 * i], v1 = acc[mt][nt][2 * i + 1];
                if (MODE == 0) {
                    const int seg = gn >> 9, nn = gn & 511;
                    const int h = nn >> 6, d = nn & 63;
                    const int bI = gm >> 11, s = gm & 2047;
                    size_t idx = ((size_t)((bI * 8 + h) * 2048 + s)) * 64 + d;
                    __half* dst = (seg == 0) ? q : (seg == 1) ? k : v;
                    *reinterpret_cast<uint32_t*>(dst + idx) = pkh(v0, v1);
                } else {
                    float2 o = make_float2(v0 + bias[gn], v1 + bias[gn + 1]);
                    *reinterpret_cast<float2*>(outp + (size_t)gm * 512 + gn) = o;
                }
            }
        }
    }
}

// ---------------- attention: single-fp16 HMMA flash, 3-stage pipeline -------
__global__ void __launch_bounds__(256, 1)
attn_mma(const __half* __restrict__ qg, const __half* __restrict__ kg,
         const __half* __restrict__ vg, const float* __restrict__ log_temp,
         __half* __restrict__ aout) {
    extern __shared__ char smc[];
    const uint32_t sb = smem_u32(smc);
    const int tid = threadIdx.x, w = tid >> 5, lane = tid & 31;
    const int q0 = blockIdx.x * 128;
    const int bh = blockIdx.y, b = bh >> 3, h = bh & 7;
    const uint32_t KO = 0, VO = 16384, STG = 32768, QO = 98304;

    const float scale = __expf(*log_temp);
    const size_t bho = (size_t)bh * 2048 * 64;

    // Q -> smem
#pragma unroll
    for (int i = tid; i < 1024; i += 256) {
        int r = i >> 3, c = i & 7;
        *reinterpret_cast<uint4*>(smc + QO + swz(r, c)) =
            *reinterpret_cast<const uint4*>(qg + bho + (size_t)(q0 + r) * 64 + c * 8);
    }

    auto issue = [&](int t, int stg) {
        const size_t o = bho + (size_t)t * 128 * 64;
        uint32_t base = sb + (uint32_t)stg * STG;
#pragma unroll
        for (int i = tid; i < 1024; i += 256) {
            int r = i >> 3, c = i & 7;
            uint32_t off = swz(r, c);
            size_t g = o + (size_t)r * 64 + c * 8;
            cp16(base + KO + off, kg + g);
            cp16(base + VO + off, vg + g);
        }
    };
    issue(0, 0); CP_COMMIT();
    issue(1, 1); CP_COMMIT();
    __syncthreads();   // Q visible

    uint32_t aq[4][4];
    {
        int rr = 16 * w + (lane & 7) + ((lane >> 3) & 1) * 8;
#pragma unroll
        for (int ks = 0; ks < 4; ks++) {
            int cc = 2 * ks + (lane >> 4);
            ldsm4(aq[ks][0], aq[ks][1], aq[ks][2], aq[ks][3], sb + QO + swz(rr, cc));
        }
    }

    float O[8][4] = {};
    float l0 = 0.f, l1 = 0.f;
    const int rg = 16 * w + (lane >> 2);
    const int qi0 = q0 + rg, qi1 = qi0 + 8;

    for (int t = 0; t < 16; t++) {
        if (t + 2 < 16) {
            int nt_ = t + 2;
            int s3 = nt_ - (nt_ >= 3 ? 3 : 0) - (nt_ >= 6 ? 3 : 0) - (nt_ >= 9 ? 3 : 0)
                   - (nt_ >= 12 ? 3 : 0) - (nt_ >= 15 ? 3 : 0);
            issue(nt_, s3);
        }
        CP_COMMIT();
        CP_WAIT2();
        __syncthreads();

        int ts = t - (t >= 3 ? 3 : 0) - (t >= 6 ? 3 : 0) - (t >= 9 ? 3 : 0)
               - (t >= 12 ? 3 : 0) - (t >= 15 ? 3 : 0);
        const uint32_t stgb = sb + (uint32_t)ts * STG;
        const uint32_t Ks = stgb + KO, Vs = stgb + VO;

        // S = Q @ K^T
        float S[16][4] = {};
#pragma unroll
        for (int ks = 0; ks < 4; ks++) {
#pragma unroll
            for (int ntp = 0; ntp < 8; ntp++) {
                uint32_t b0, b1, b2, b3;
                int rr = 16 * ntp + (lane & 7) + ((lane >> 4) ? 8 : 0);
                int cc = 2 * ks + ((lane >> 3) & 1);
                ldsm4(b0, b1, b2, b3, Ks + swz(rr, cc));
                mma_f16(S[2 * ntp],     aq[ks], b0, b1);
                mma_f16(S[2 * ntp + 1], aq[ks], b2, b3);
            }
        }

        // exp + diag mask, pack P to fp16
        const int j00 = t * 128 + 2 * (lane & 3);
        uint32_t ep[16][2];
#pragma unroll
        for (int nt = 0; nt < 16; nt++) {
            int jc = j00 + 8 * nt;
            float e0 = (jc     == qi0) ? 0.f : __expf(S[nt][0] * scale);
            float e1 = (jc + 1 == qi0) ? 0.f : __expf(S[nt][1] * scale);
            float e2 = (jc     == qi1) ? 0.f : __expf(S[nt][2] * scale);
            float e3 = (jc + 1 == qi1) ? 0.f : __expf(S[nt][3] * scale);
            l0 += e0 + e1;
            l1 += e2 + e3;
            ep[nt][0] = pkh(e0, e1);
            ep[nt][1] = pkh(e2, e3);
        }

        // O += P @ V
#pragma unroll
        for (int ks = 0; ks < 8; ks++) {
            uint32_t ap[4] = { ep[2 * ks][0], ep[2 * ks][1],
                               ep[2 * ks + 1][0], ep[2 * ks + 1][1] };
#pragma unroll
            for (int ntp = 0; ntp < 4; ntp++) {
                uint32_t b0, b1, b2, b3;
                int rr = 16 * ks + (lane & 7) + ((lane >> 3) & 1) * 8;
                int cc = 2 * ntp + (lane >> 4);
                ldsm4t(b0, b1, b2, b3, Vs + swz(rr, cc));
                mma_f16(O[2 * ntp],     ap, b0, b1);
                mma_f16(O[2 * ntp + 1], ap, b2, b3);
            }
        }
        __syncthreads();
    }

    l0 += __shfl_xor_sync(0xffffffffu, l0, 1);
    l0 += __shfl_xor_sync(0xffffffffu, l0, 2);
    l1 += __shfl_xor_sync(0xffffffffu, l1, 1);
    l1 += __shfl_xor_sync(0xffffffffu, l1, 2);
    const float inv0 = 1.f / l0, inv1 = 1.f / l1;

#pragma unroll
    for (int i = 0; i < 2; i++) {
        const float inv = i ? inv1 : inv0;
        const size_t gm = (size_t)(b * 2048 + q0 + rg + i * 8);
#pragma unroll
        for (int nt = 0; nt < 8; nt++) {
            const int d = 8 * nt + 2 * (lane & 3);
            size_t idx = gm * INNER + h * DHEAD + d;
            *reinterpret_cast<uint32_t*>(aout + idx) =
                pkh(O[nt][2 * i] * inv, O[nt][2 * i + 1] * inv);
        }
    }
}

// ---------------- launch -----------------------------------------------------
extern "C" void kernel_launch(void* const* d_in, const int* in_sizes, int n_in,
                              void* d_out, int out_size) {
    const float* x        = (const float*)d_in[0];
    const float* W_qkv    = (const float*)d_in[1];
    const float* log_temp = (const float*)d_in[2];
    const float* W_out    = (const float*)d_in[3];
    const float* b_out    = (const float*)d_in[4];
    float* out = (float*)d_out;

    __half *xh, *xl, *wqh, *wql, *woh, *q, *k, *v, *a;
    cudaGetSymbolAddress((void**)&xh, g_xh);   cudaGetSymbolAddress((void**)&xl, g_xl);
    cudaGetSymbolAddress((void**)&wqh, g_wqh); cudaGetSymbolAddress((void**)&wql, g_wql);
    cudaGetSymbolAddress((void**)&woh, g_woh);
    cudaGetSymbolAddress((void**)&q, g_q);
    cudaGetSymbolAddress((void**)&k, g_k);
    cudaGetSymbolAddress((void**)&v, g_v);
    cudaGetSymbolAddress((void**)&a, g_a);

    const int GSM = 131072;
    const int ASM = 114688;
    cudaFuncSetAttribute(gemm_mma<0>, cudaFuncAttributeMaxDynamicSharedMemorySize, GSM);
    cudaFuncSetAttribute(gemm_mma<1>, cudaFuncAttributeMaxDynamicSharedMemorySize, GSM);
    cudaFuncSetAttribute(attn_mma,    cudaFuncAttributeMaxDynamicSharedMemorySize, ASM);

    k_split_h<<<(NROWS * DIMX + 255) / 256, 256>>>(x, xh, xl, NROWS * DIMX);
    k_splitT_h<true><<<(DIMX * 3 * INNER + 255) / 256, 256>>>(W_qkv, wqh, wql,
                                                              DIMX, 3 * INNER);
    k_splitT_h<false><<<(INNER * DIMX + 255) / 256, 256>>>(W_out, woh, nullptr,
                                                           INNER, DIMX);

    // 1) QKV projection: q/k tiles 3-term fp16x3, V tiles 1-term fp16
    gemm_mma<0><<<dim3(12, 64), 512, GSM>>>(xh, xl, wqh, wql, DIMX,
                                            q, k, v, nullptr, nullptr);
    // 2) attention (single fp16, at pipe floor)
    attn_mma<<<dim3(SSEQ / 128, BB * HEADS), 256, ASM>>>(q, k, v, log_temp, a);
    // 3) output projection, 1-term fp16 + bias -> fp32
    gemm_mma<1><<<dim3(4, 64), 512, GSM>>>(a, a, woh, woh, INNER,
                                           nullptr, nullptr, nullptr, b_out, out);
}